// round 12
// baseline (speedup 1.0000x reference)
#include <cuda_runtime.h>
#include <cuda_bf16.h>
#include <cuda_fp16.h>
#include <cstdint>

// LinkPredictorGAT: N_NODES=100000, D=256, E=1000000, H=128
// out_e = relu(z[src]@W1[:256] + z[dst]@W1[256:] + b1) @ W2 + b2
//
// Stage 0: W1 -> WT fp16, transposed to [N=256,K=256] K-major.
// Stage 1: fp16 HMMA GEMM, CTA tile 128x128, 2 CTAs/SM, fully unrolled chunks:
//          LDG Z fp32 -> cvt fp16 -> STS.128 (dbl-buf); cp.async WT (dbl-buf,
//          issued AFTER the sync — stage (c+1)&1 readers must be done first).
//          UV[M,256](fp16) = Z16@W16 (+b1 on cols<128).
// Stage 2: 4 edges/warp on fp16 UV: out = relu(u[src]+v[dst]) . W2 + b2

#define MAX_NODES 100000
#define DD 256
#define HH 128

__device__ __half g_UV[(size_t)MAX_NODES * 2 * HH];     // 51.2 MB
__device__ __half g_WT[256 * 256];                      // 128 KB

__device__ __forceinline__ uint32_t smem_u32(const void* p) {
    uint32_t a;
    asm("{ .reg .u64 t; cvta.to.shared.u64 t, %1; cvt.u32.u64 %0, t; }" : "=r"(a) : "l"(p));
    return a;
}

#define CP_ASYNC16(dst, src) \
    asm volatile("cp.async.cg.shared.global [%0], [%1], 16;" :: "r"(dst), "l"(src) : "memory")
#define CP_COMMIT() asm volatile("cp.async.commit_group;" ::: "memory")
#define CP_WAIT_0() asm volatile("cp.async.wait_group 0;" ::: "memory")

#define LDMATRIX_X4(r0, r1, r2, r3, addr) \
    asm volatile("ldmatrix.sync.aligned.m8n8.x4.shared.b16 {%0,%1,%2,%3}, [%4];" \
                 : "=r"(r0), "=r"(r1), "=r"(r2), "=r"(r3) : "r"(addr))

#define MMA_F16(d, a0, a1, a2, a3, b0, b1) \
    asm volatile("mma.sync.aligned.m16n8k16.row.col.f32.f16.f16.f32 " \
                 "{%0,%1,%2,%3}, {%4,%5,%6,%7}, {%8,%9}, {%0,%1,%2,%3};" \
                 : "+f"((d)[0]), "+f"((d)[1]), "+f"((d)[2]), "+f"((d)[3]) \
                 : "r"(a0), "r"(a1), "r"(a2), "r"(a3), "r"(b0), "r"(b1))

// ---------------- Stage 0: build transposed fp16 W ----------------
__global__ __launch_bounds__(256)
void split_w_kernel(const float* __restrict__ W1, __half* __restrict__ WT) {
    int idx = blockIdx.x * blockDim.x + threadIdx.x;
    if (idx >= 256 * 256) return;
    int n = idx & 255;
    int k = idx >> 8;
    float val = (n < HH) ? W1[(size_t)k * HH + n]
                         : W1[(size_t)(256 + k) * HH + (n - HH)];
    WT[(size_t)n * 256 + k] = __float2half_rn(val);
}

// ---------------- Stage 1: fp16 HMMA GEMM, 128x128 tile ----------------
// SMEM (64 KB), stages s in {0,1}:
//   A(s) @ s*16384                 [0, 32K)
//   B(s) @ 32768 + s*16384         [32K, 64K)
#define A_OFF(s)  ((s) * 16384)
#define B_OFF(s)  (32768 + (s) * 16384)
#define GSM_TOTAL 65536

__global__ __launch_bounds__(256, 2)
void uv_gemm_fused_kernel(const float* __restrict__ Z,
                          const __half* __restrict__ WT,
                          const float* __restrict__ b1,
                          __half* __restrict__ UV,
                          int M) {
    extern __shared__ char smem[];
    const uint32_t sbase = smem_u32(smem);
    const int tid  = threadIdx.x;
    const int wid  = tid >> 5;
    const int lane = tid & 31;
    const int wm   = wid & 3;          // 4 warp-row groups: 32 rows each
    const int wn   = wid >> 2;         // 2 warp-col groups: 64 cols each
    const int row0 = blockIdx.x * 128;
    const int col0 = blockIdx.y * 128; // N-half of WT

    const int g  = lane >> 3;
    const int lr = lane & 7;
    const int uAbit = g >> 1;
    const int uBbit = g & 1;
    const int rA0 = wm * 32 + (g & 1) * 8 + lr;
    const int nB0 = wn * 64 + (g >> 1) * 8 + lr;   // within 128-row B tile

    float acc[2][8][4];
#pragma unroll
    for (int mi = 0; mi < 2; mi++)
#pragma unroll
        for (int ni = 0; ni < 8; ni++)
#pragma unroll
            for (int q = 0; q < 4; q++) acc[mi][ni][q] = 0.f;

    // A path: per thread 4 items; item = 32B fp32 of one row -> 16B fp16 STS.128
    auto ldg_A = [&](int c, float4 (&rA)[4][2]) {
        const int kc = c * 64;
#pragma unroll
        for (int i = 0; i < 4; ++i) {
            int idx = tid + i * 256;
            int r = idx >> 3;
            int p = idx & 7;
            int gr = row0 + r; if (gr > M - 1) gr = M - 1;
            const float4* src = reinterpret_cast<const float4*>(Z + (size_t)gr * 256 + kc + p * 8);
            rA[i][0] = __ldg(src);
            rA[i][1] = __ldg(src + 1);
        }
    };
    auto sts_A = [&](int s, const float4 (&rA)[4][2]) {
#pragma unroll
        for (int i = 0; i < 4; ++i) {
            int idx = tid + i * 256;
            int r = idx >> 3;
            int p = idx & 7;
            __half2 h0 = __floats2half2_rn(rA[i][0].x, rA[i][0].y);
            __half2 h1 = __floats2half2_rn(rA[i][0].z, rA[i][0].w);
            __half2 h2 = __floats2half2_rn(rA[i][1].x, rA[i][1].y);
            __half2 h3 = __floats2half2_rn(rA[i][1].z, rA[i][1].w);
            uint4 hv = make_uint4(*reinterpret_cast<uint32_t*>(&h0),
                                  *reinterpret_cast<uint32_t*>(&h1),
                                  *reinterpret_cast<uint32_t*>(&h2),
                                  *reinterpret_cast<uint32_t*>(&h3));
            uint32_t soff = (uint32_t)(r * 128 + ((p ^ (r & 7)) << 4));
            *reinterpret_cast<uint4*>(smem + A_OFF(s) + soff) = hv;
        }
    };
    auto issue_B = [&](int c) {
        const int kc = c * 64;
        const int s  = c & 1;
#pragma unroll
        for (int i = 0; i < 4; ++i) {
            int idx = tid + i * 256;
            int n = idx >> 3;                      // 0..127
            int u = idx & 7;
            uint32_t soff = (uint32_t)(n * 128 + ((u ^ (n & 7)) << 4));
            CP_ASYNC16(sbase + B_OFF(s) + soff, WT + (size_t)(col0 + n) * 256 + kc + u * 8);
        }
        CP_COMMIT();
    };

    // ---- prologue ----
    float4 rA[4][2];
    ldg_A(0, rA);
    issue_B(0);
    sts_A(0, rA);
    ldg_A(1, rA);

#pragma unroll
    for (int c = 0; c < 4; ++c) {
        CP_WAIT_0();            // B(c) landed
        __syncthreads();        // stage (c+1)&1 readers (iter c-1 MMA) are done

        if (c < 3) issue_B(c + 1);   // safe: after the sync; lands during MMA(c)

        const int s = c & 1;
        const uint32_t aBase = sbase + A_OFF(s);
        const uint32_t bBase = sbase + B_OFF(s);

#pragma unroll
        for (int kk = 0; kk < 4; ++kk) {
            uint32_t af[2][4];
#pragma unroll
            for (int mi = 0; mi < 2; ++mi) {
                int r = rA0 + mi * 16;
                uint32_t aoff = (uint32_t)(r * 128 + (((kk * 2 + uAbit) ^ lr) << 4));
                LDMATRIX_X4(af[mi][0], af[mi][1], af[mi][2], af[mi][3], aBase + aoff);
            }
#pragma unroll
            for (int np = 0; np < 4; ++np) {
                int n = nB0 + np * 16;
                uint32_t boff = (uint32_t)(n * 128 + (((kk * 2 + uBbit) ^ lr) << 4));
                uint32_t b0, b1r, b2, b3;
                LDMATRIX_X4(b0, b1r, b2, b3, bBase + boff);
#pragma unroll
                for (int mi = 0; mi < 2; ++mi) {
                    MMA_F16(acc[mi][np * 2],     af[mi][0], af[mi][1], af[mi][2], af[mi][3], b0, b1r);
                    MMA_F16(acc[mi][np * 2 + 1], af[mi][0], af[mi][1], af[mi][2], af[mi][3], b2, b3);
                }
            }
        }

        if (c < 3) {
            sts_A((c + 1) & 1, rA);
            if (c < 2) ldg_A(c + 2, rA);
        }
    }

    // ---- epilogue: +b1 on cols<128, store fp16 ----
    const int trow  = lane >> 2;
    const int tcol2 = (lane & 3) * 2;
#pragma unroll
    for (int mi = 0; mi < 2; ++mi) {
#pragma unroll
        for (int ni = 0; ni < 8; ++ni) {
            int col = col0 + wn * 64 + ni * 8 + tcol2;
            float bx = 0.f, by = 0.f;
            if (col < HH) { bx = __ldg(&b1[col]); by = __ldg(&b1[col + 1]); }
#pragma unroll
            for (int h = 0; h < 2; ++h) {
                int r = row0 + wm * 32 + mi * 16 + trow + h * 8;
                if (r < M) {
                    __half2 v = __floats2half2_rn(acc[mi][ni][h * 2] + bx,
                                                  acc[mi][ni][h * 2 + 1] + by);
                    *reinterpret_cast<__half2*>(UV + (size_t)r * 256 + col) = v;
                }
            }
        }
    }
}

// ---------------- Stage 2: 4 edges per warp, fp16 UV ----------------
__global__ __launch_bounds__(256)
void edge_kernel(const int* __restrict__ eli,
                 const __half* __restrict__ UV,
                 const float* __restrict__ W2,
                 const float* __restrict__ b2,
                 float* __restrict__ out,
                 int E) {
    int gwarp = (blockIdx.x * blockDim.x + threadIdx.x) >> 5;
    int lane  = threadIdx.x & 31;
    int e0 = gwarp * 4;
    if (e0 >= E) return;

    float4 w = __ldg(reinterpret_cast<const float4*>(W2) + lane);

    int s[4], d[4];
#pragma unroll
    for (int i = 0; i < 4; ++i) {
        int e = min(e0 + i, E - 1);
        s[i] = __ldg(&eli[e]);
        d[i] = __ldg(&eli[(size_t)E + e]);
    }
    uint2 ur[4], vr[4];
#pragma unroll
    for (int i = 0; i < 4; ++i) {
        ur[i] = __ldg(reinterpret_cast<const uint2*>(UV + (size_t)s[i] * 256) + lane);
        vr[i] = __ldg(reinterpret_cast<const uint2*>(UV + (size_t)d[i] * 256 + HH) + lane);
    }
    float p[4];
#pragma unroll
    for (int i = 0; i < 4; ++i) {
        const __half2* uh = reinterpret_cast<const __half2*>(&ur[i]);
        const __half2* vh = reinterpret_cast<const __half2*>(&vr[i]);
        float2 u01 = __half22float2(uh[0]);
        float2 u23 = __half22float2(uh[1]);
        float2 v01 = __half22float2(vh[0]);
        float2 v23 = __half22float2(vh[1]);
        p[i] = fmaxf(u01.x + v01.x, 0.f) * w.x + fmaxf(u01.y + v01.y, 0.f) * w.y
             + fmaxf(u23.x + v23.x, 0.f) * w.z + fmaxf(u23.y + v23.y, 0.f) * w.w;
    }
#pragma unroll
    for (int o = 16; o > 0; o >>= 1) {
#pragma unroll
        for (int i = 0; i < 4; ++i)
            p[i] += __shfl_down_sync(0xffffffffu, p[i], o);
    }
    if (lane == 0) {
        float bb = __ldg(b2);
#pragma unroll
        for (int i = 0; i < 4; ++i)
            if (e0 + i < E) out[e0 + i] = p[i] + bb;
    }
}

extern "C" void kernel_launch(void* const* d_in, const int* in_sizes, int n_in,
                              void* d_out, int out_size) {
    const float* z   = (const float*)d_in[0];
    const int*   eli = (const int*)d_in[1];
    const float* W1  = (const float*)d_in[2];
    const float* b1  = (const float*)d_in[3];
    const float* W2  = (const float*)d_in[4];
    const float* b2  = (const float*)d_in[5];
    float*       out = (float*)d_out;

    const int M = in_sizes[0] / DD;
    const int E = out_size;

    __half *UV, *WT;
    cudaGetSymbolAddress((void**)&UV, g_UV);
    cudaGetSymbolAddress((void**)&WT, g_WT);

    cudaFuncSetAttribute(uv_gemm_fused_kernel,
                         cudaFuncAttributeMaxDynamicSharedMemorySize, GSM_TOTAL);

    split_w_kernel<<<(256 * 256 + 255) / 256, 256>>>(W1, WT);

    dim3 ggrid((M + 127) / 128, 2);
    uv_gemm_fused_kernel<<<ggrid, 256, GSM_TOTAL>>>(z, WT, b1, UV, M);

    int quads = (E + 3) / 4;
    int warpsPerBlock = 256 / 32;
    int nblk = (quads + warpsPerBlock - 1) / warpsPerBlock;
    edge_kernel<<<nblk, 256>>>(eli, UV, W2, b2, out, E);
}

// round 13
// speedup vs baseline: 1.1239x; 1.1239x over previous
#include <cuda_runtime.h>
#include <cuda_bf16.h>
#include <cuda_fp16.h>
#include <cstdint>

// LinkPredictorGAT: N_NODES=100000, D=256, E=1000000, H=128
// out_e = relu(z[src]@W1[:256] + z[dst]@W1[256:] + b1) @ W2 + b2
//
// Stage 0: W1 -> WT fp16, transposed to [N=256,K=256] K-major.
// Stage 1: fp16 HMMA GEMM, CTA tile 128x128, 2 CTAs/SM:
//          LDG Z fp32 -> cvt fp16 -> STS (dbl-buf); cp.async WT (dbl-buf).
//          UV[M,256](fp16) = Z16@W16 (+b1 on cols<128).
// Stage 2: 4 edges/warp on fp16 UV: out = relu(u[src]+v[dst]) . W2 + b2
//
// (Round-10 configuration — measured optimum. Rounds 11/12 variants of the
//  GEMM inner loop both regressed; GEMM sits at the mma.sync issue floor,
//  edge kernel at the LTS chip cap.)

#define MAX_NODES 100000
#define DD 256
#define HH 128

__device__ __half g_UV[(size_t)MAX_NODES * 2 * HH];     // 51.2 MB
__device__ __half g_WT[256 * 256];                      // 128 KB

__device__ __forceinline__ uint32_t smem_u32(const void* p) {
    uint32_t a;
    asm("{ .reg .u64 t; cvta.to.shared.u64 t, %1; cvt.u32.u64 %0, t; }" : "=r"(a) : "l"(p));
    return a;
}

#define CP_ASYNC16(dst, src) \
    asm volatile("cp.async.cg.shared.global [%0], [%1], 16;" :: "r"(dst), "l"(src) : "memory")
#define CP_COMMIT() asm volatile("cp.async.commit_group;" ::: "memory")
#define CP_WAIT_0() asm volatile("cp.async.wait_group 0;" ::: "memory")

#define LDMATRIX_X4(r0, r1, r2, r3, addr) \
    asm volatile("ldmatrix.sync.aligned.m8n8.x4.shared.b16 {%0,%1,%2,%3}, [%4];" \
                 : "=r"(r0), "=r"(r1), "=r"(r2), "=r"(r3) : "r"(addr))

#define MMA_F16(d, a0, a1, a2, a3, b0, b1) \
    asm volatile("mma.sync.aligned.m16n8k16.row.col.f32.f16.f16.f32 " \
                 "{%0,%1,%2,%3}, {%4,%5,%6,%7}, {%8,%9}, {%0,%1,%2,%3};" \
                 : "+f"((d)[0]), "+f"((d)[1]), "+f"((d)[2]), "+f"((d)[3]) \
                 : "r"(a0), "r"(a1), "r"(a2), "r"(a3), "r"(b0), "r"(b1))

// ---------------- Stage 0: build transposed fp16 W ----------------
__global__ __launch_bounds__(256)
void split_w_kernel(const float* __restrict__ W1, __half* __restrict__ WT) {
    int idx = blockIdx.x * blockDim.x + threadIdx.x;
    if (idx >= 256 * 256) return;
    int n = idx & 255;
    int k = idx >> 8;
    float val = (n < HH) ? W1[(size_t)k * HH + n]
                         : W1[(size_t)(256 + k) * HH + (n - HH)];
    WT[(size_t)n * 256 + k] = __float2half_rn(val);
}

// ---------------- Stage 1: fp16 HMMA GEMM, 128x128 tile ----------------
// SMEM (64 KB), stages s in {0,1}:
//   A(s) @ s*16384                 [0, 32K)
//   B(s) @ 32768 + s*16384         [32K, 64K)
#define A_OFF(s)  ((s) * 16384)
#define B_OFF(s)  (32768 + (s) * 16384)
#define GSM_TOTAL 65536

__global__ __launch_bounds__(256, 2)
void uv_gemm_fused_kernel(const float* __restrict__ Z,
                          const __half* __restrict__ WT,
                          const float* __restrict__ b1,
                          __half* __restrict__ UV,
                          int M) {
    extern __shared__ char smem[];
    const uint32_t sbase = smem_u32(smem);
    const int tid  = threadIdx.x;
    const int wid  = tid >> 5;
    const int lane = tid & 31;
    const int wm   = wid & 3;          // 4 warp-row groups: 32 rows each
    const int wn   = wid >> 2;         // 2 warp-col groups: 64 cols each
    const int row0 = blockIdx.x * 128;
    const int col0 = blockIdx.y * 128; // N-half of WT

    const int g  = lane >> 3;
    const int lr = lane & 7;
    const int uAbit = g >> 1;
    const int uBbit = g & 1;
    const int rA0 = wm * 32 + (g & 1) * 8 + lr;
    const int nB0 = wn * 64 + (g >> 1) * 8 + lr;   // within 128-row B tile

    float acc[2][8][4];
#pragma unroll
    for (int mi = 0; mi < 2; mi++)
#pragma unroll
        for (int ni = 0; ni < 8; ni++)
#pragma unroll
            for (int q = 0; q < 4; q++) acc[mi][ni][q] = 0.f;

    auto ldg_A = [&](int c, float4 (&rA)[8]) {
        const int kc = c * 64;
#pragma unroll
        for (int i = 0; i < 8; ++i) {
            int idx = tid + i * 256;
            int r = idx >> 4;
            int q = idx & 15;
            int gr = row0 + r; if (gr > M - 1) gr = M - 1;
            rA[i] = __ldg(reinterpret_cast<const float4*>(Z + (size_t)gr * 256 + kc + q * 4));
        }
    };
    auto sts_A = [&](int s, const float4 (&rA)[8]) {
#pragma unroll
        for (int i = 0; i < 8; ++i) {
            int idx = tid + i * 256;
            int r = idx >> 4;
            int q = idx & 15;
            float4 f = rA[i];
            __half2 h01 = __floats2half2_rn(f.x, f.y);
            __half2 h23 = __floats2half2_rn(f.z, f.w);
            uint2 hv = make_uint2(*reinterpret_cast<uint32_t*>(&h01),
                                  *reinterpret_cast<uint32_t*>(&h23));
            uint32_t soff = (uint32_t)(r * 128 + (((q >> 1) ^ (r & 7)) << 4) + (q & 1) * 8);
            *reinterpret_cast<uint2*>(smem + A_OFF(s) + soff) = hv;
        }
    };
    auto issue_B = [&](int c) {
        const int kc = c * 64;
        const int s  = c & 1;
#pragma unroll
        for (int i = 0; i < 4; ++i) {
            int idx = tid + i * 256;
            int n = idx >> 3;                      // 0..127
            int u = idx & 7;
            uint32_t soff = (uint32_t)(n * 128 + ((u ^ (n & 7)) << 4));
            CP_ASYNC16(sbase + B_OFF(s) + soff, WT + (size_t)(col0 + n) * 256 + kc + u * 8);
        }
        CP_COMMIT();
    };

    // ---- prologue ----
    float4 rA[8];
    ldg_A(0, rA);
    issue_B(0);
    sts_A(0, rA);
    ldg_A(1, rA);

    for (int c = 0; c < 4; ++c) {
        CP_WAIT_0();
        __syncthreads();

        if (c < 3) issue_B(c + 1);

        const int s = c & 1;
        const uint32_t aBase = sbase + A_OFF(s);
        const uint32_t bBase = sbase + B_OFF(s);

#pragma unroll
        for (int kk = 0; kk < 4; ++kk) {
            uint32_t af[2][4];
#pragma unroll
            for (int mi = 0; mi < 2; ++mi) {
                int r = rA0 + mi * 16;
                uint32_t aoff = (uint32_t)(r * 128 + (((kk * 2 + uAbit) ^ lr) << 4));
                LDMATRIX_X4(af[mi][0], af[mi][1], af[mi][2], af[mi][3], aBase + aoff);
            }
#pragma unroll
            for (int np = 0; np < 4; ++np) {
                int n = nB0 + np * 16;
                uint32_t boff = (uint32_t)(n * 128 + (((kk * 2 + uBbit) ^ lr) << 4));
                uint32_t b0, b1r, b2, b3;
                LDMATRIX_X4(b0, b1r, b2, b3, bBase + boff);
#pragma unroll
                for (int mi = 0; mi < 2; ++mi) {
                    MMA_F16(acc[mi][np * 2],     af[mi][0], af[mi][1], af[mi][2], af[mi][3], b0, b1r);
                    MMA_F16(acc[mi][np * 2 + 1], af[mi][0], af[mi][1], af[mi][2], af[mi][3], b2, b3);
                }
            }
        }

        if (c < 3) {
            sts_A((c + 1) & 1, rA);
            if (c < 2) ldg_A(c + 2, rA);
        }
    }

    // ---- epilogue: +b1 on cols<128, store fp16 ----
    const int trow  = lane >> 2;
    const int tcol2 = (lane & 3) * 2;
#pragma unroll
    for (int mi = 0; mi < 2; ++mi) {
#pragma unroll
        for (int ni = 0; ni < 8; ++ni) {
            int col = col0 + wn * 64 + ni * 8 + tcol2;
            float bx = 0.f, by = 0.f;
            if (col < HH) { bx = __ldg(&b1[col]); by = __ldg(&b1[col + 1]); }
#pragma unroll
            for (int h = 0; h < 2; ++h) {
                int r = row0 + wm * 32 + mi * 16 + trow + h * 8;
                if (r < M) {
                    __half2 v = __floats2half2_rn(acc[mi][ni][h * 2] + bx,
                                                  acc[mi][ni][h * 2 + 1] + by);
                    *reinterpret_cast<__half2*>(UV + (size_t)r * 256 + col) = v;
                }
            }
        }
    }
}

// ---------------- Stage 2: 4 edges per warp, fp16 UV ----------------
__global__ __launch_bounds__(256)
void edge_kernel(const int* __restrict__ eli,
                 const __half* __restrict__ UV,
                 const float* __restrict__ W2,
                 const float* __restrict__ b2,
                 float* __restrict__ out,
                 int E) {
    int gwarp = (blockIdx.x * blockDim.x + threadIdx.x) >> 5;
    int lane  = threadIdx.x & 31;
    int e0 = gwarp * 4;
    if (e0 >= E) return;

    float4 w = __ldg(reinterpret_cast<const float4*>(W2) + lane);

    int s[4], d[4];
#pragma unroll
    for (int i = 0; i < 4; ++i) {
        int e = min(e0 + i, E - 1);
        s[i] = __ldg(&eli[e]);
        d[i] = __ldg(&eli[(size_t)E + e]);
    }
    uint2 ur[4], vr[4];
#pragma unroll
    for (int i = 0; i < 4; ++i) {
        ur[i] = __ldg(reinterpret_cast<const uint2*>(UV + (size_t)s[i] * 256) + lane);
        vr[i] = __ldg(reinterpret_cast<const uint2*>(UV + (size_t)d[i] * 256 + HH) + lane);
    }
    float p[4];
#pragma unroll
    for (int i = 0; i < 4; ++i) {
        const __half2* uh = reinterpret_cast<const __half2*>(&ur[i]);
        const __half2* vh = reinterpret_cast<const __half2*>(&vr[i]);
        float2 u01 = __half22float2(uh[0]);
        float2 u23 = __half22float2(uh[1]);
        float2 v01 = __half22float2(vh[0]);
        float2 v23 = __half22float2(vh[1]);
        p[i] = fmaxf(u01.x + v01.x, 0.f) * w.x + fmaxf(u01.y + v01.y, 0.f) * w.y
             + fmaxf(u23.x + v23.x, 0.f) * w.z + fmaxf(u23.y + v23.y, 0.f) * w.w;
    }
#pragma unroll
    for (int o = 16; o > 0; o >>= 1) {
#pragma unroll
        for (int i = 0; i < 4; ++i)
            p[i] += __shfl_down_sync(0xffffffffu, p[i], o);
    }
    if (lane == 0) {
        float bb = __ldg(b2);
#pragma unroll
        for (int i = 0; i < 4; ++i)
            if (e0 + i < E) out[e0 + i] = p[i] + bb;
    }
}

extern "C" void kernel_launch(void* const* d_in, const int* in_sizes, int n_in,
                              void* d_out, int out_size) {
    const float* z   = (const float*)d_in[0];
    const int*   eli = (const int*)d_in[1];
    const float* W1  = (const float*)d_in[2];
    const float* b1  = (const float*)d_in[3];
    const float* W2  = (const float*)d_in[4];
    const float* b2  = (const float*)d_in[5];
    float*       out = (float*)d_out;

    const int M = in_sizes[0] / DD;
    const int E = out_size;

    __half *UV, *WT;
    cudaGetSymbolAddress((void**)&UV, g_UV);
    cudaGetSymbolAddress((void**)&WT, g_WT);

    cudaFuncSetAttribute(uv_gemm_fused_kernel,
                         cudaFuncAttributeMaxDynamicSharedMemorySize, GSM_TOTAL);

    split_w_kernel<<<(256 * 256 + 255) / 256, 256>>>(W1, WT);

    dim3 ggrid((M + 127) / 128, 2);
    uv_gemm_fused_kernel<<<ggrid, 256, GSM_TOTAL>>>(z, WT, b1, UV, M);

    int quads = (E + 3) / 4;
    int warpsPerBlock = 256 / 32;
    int nblk = (quads + warpsPerBlock - 1) / warpsPerBlock;
    edge_kernel<<<nblk, 256>>>(eli, UV, W2, b2, out, E);
}

// round 14
// speedup vs baseline: 1.1473x; 1.0208x over previous
#include <cuda_runtime.h>
#include <cuda_bf16.h>
#include <cuda_fp16.h>
#include <cstdint>

// LinkPredictorGAT: N_NODES=100000, D=256, E=1000000, H=128
// out_e = relu(z[src]@W1[:256] + z[dst]@W1[256:] + b1) @ W2 + b2
//
// Stage 0: W1 -> WT fp16, transposed to [N=256,K=256] K-major.
// Stage 1: fp16 HMMA GEMM, CTA tile 128x128, 2 CTAs/SM (round-10 optimum):
//          LDG Z fp32 -> cvt fp16 -> STS (dbl-buf); cp.async WT (dbl-buf).
//          UV[M,256](fp16) = Z16@W16 (+b1 on cols<128).
// Stage 2: 8 edges/warp on fp16 UV, L2-only gathers (__ldcg — UV is L2-resident
//          but far exceeds L1, so L1 was pure overhead):
//          out = relu(u[src]+v[dst]) . W2 + b2

#define MAX_NODES 100000
#define DD 256
#define HH 128

__device__ __half g_UV[(size_t)MAX_NODES * 2 * HH];     // 51.2 MB
__device__ __half g_WT[256 * 256];                      // 128 KB

__device__ __forceinline__ uint32_t smem_u32(const void* p) {
    uint32_t a;
    asm("{ .reg .u64 t; cvta.to.shared.u64 t, %1; cvt.u32.u64 %0, t; }" : "=r"(a) : "l"(p));
    return a;
}

#define CP_ASYNC16(dst, src) \
    asm volatile("cp.async.cg.shared.global [%0], [%1], 16;" :: "r"(dst), "l"(src) : "memory")
#define CP_COMMIT() asm volatile("cp.async.commit_group;" ::: "memory")
#define CP_WAIT_0() asm volatile("cp.async.wait_group 0;" ::: "memory")

#define LDMATRIX_X4(r0, r1, r2, r3, addr) \
    asm volatile("ldmatrix.sync.aligned.m8n8.x4.shared.b16 {%0,%1,%2,%3}, [%4];" \
                 : "=r"(r0), "=r"(r1), "=r"(r2), "=r"(r3) : "r"(addr))

#define MMA_F16(d, a0, a1, a2, a3, b0, b1) \
    asm volatile("mma.sync.aligned.m16n8k16.row.col.f32.f16.f16.f32 " \
                 "{%0,%1,%2,%3}, {%4,%5,%6,%7}, {%8,%9}, {%0,%1,%2,%3};" \
                 : "+f"((d)[0]), "+f"((d)[1]), "+f"((d)[2]), "+f"((d)[3]) \
                 : "r"(a0), "r"(a1), "r"(a2), "r"(a3), "r"(b0), "r"(b1))

// ---------------- Stage 0: build transposed fp16 W ----------------
__global__ __launch_bounds__(256)
void split_w_kernel(const float* __restrict__ W1, __half* __restrict__ WT) {
    int idx = blockIdx.x * blockDim.x + threadIdx.x;
    if (idx >= 256 * 256) return;
    int n = idx & 255;
    int k = idx >> 8;
    float val = (n < HH) ? W1[(size_t)k * HH + n]
                         : W1[(size_t)(256 + k) * HH + (n - HH)];
    WT[(size_t)n * 256 + k] = __float2half_rn(val);
}

// ---------------- Stage 1: fp16 HMMA GEMM, 128x128 tile ----------------
// SMEM (64 KB), stages s in {0,1}:
//   A(s) @ s*16384                 [0, 32K)
//   B(s) @ 32768 + s*16384         [32K, 64K)
#define A_OFF(s)  ((s) * 16384)
#define B_OFF(s)  (32768 + (s) * 16384)
#define GSM_TOTAL 65536

__global__ __launch_bounds__(256, 2)
void uv_gemm_fused_kernel(const float* __restrict__ Z,
                          const __half* __restrict__ WT,
                          const float* __restrict__ b1,
                          __half* __restrict__ UV,
                          int M) {
    extern __shared__ char smem[];
    const uint32_t sbase = smem_u32(smem);
    const int tid  = threadIdx.x;
    const int wid  = tid >> 5;
    const int lane = tid & 31;
    const int wm   = wid & 3;          // 4 warp-row groups: 32 rows each
    const int wn   = wid >> 2;         // 2 warp-col groups: 64 cols each
    const int row0 = blockIdx.x * 128;
    const int col0 = blockIdx.y * 128; // N-half of WT

    const int g  = lane >> 3;
    const int lr = lane & 7;
    const int uAbit = g >> 1;
    const int uBbit = g & 1;
    const int rA0 = wm * 32 + (g & 1) * 8 + lr;
    const int nB0 = wn * 64 + (g >> 1) * 8 + lr;   // within 128-row B tile

    float acc[2][8][4];
#pragma unroll
    for (int mi = 0; mi < 2; mi++)
#pragma unroll
        for (int ni = 0; ni < 8; ni++)
#pragma unroll
            for (int q = 0; q < 4; q++) acc[mi][ni][q] = 0.f;

    auto ldg_A = [&](int c, float4 (&rA)[8]) {
        const int kc = c * 64;
#pragma unroll
        for (int i = 0; i < 8; ++i) {
            int idx = tid + i * 256;
            int r = idx >> 4;
            int q = idx & 15;
            int gr = row0 + r; if (gr > M - 1) gr = M - 1;
            rA[i] = __ldg(reinterpret_cast<const float4*>(Z + (size_t)gr * 256 + kc + q * 4));
        }
    };
    auto sts_A = [&](int s, const float4 (&rA)[8]) {
#pragma unroll
        for (int i = 0; i < 8; ++i) {
            int idx = tid + i * 256;
            int r = idx >> 4;
            int q = idx & 15;
            float4 f = rA[i];
            __half2 h01 = __floats2half2_rn(f.x, f.y);
            __half2 h23 = __floats2half2_rn(f.z, f.w);
            uint2 hv = make_uint2(*reinterpret_cast<uint32_t*>(&h01),
                                  *reinterpret_cast<uint32_t*>(&h23));
            uint32_t soff = (uint32_t)(r * 128 + (((q >> 1) ^ (r & 7)) << 4) + (q & 1) * 8);
            *reinterpret_cast<uint2*>(smem + A_OFF(s) + soff) = hv;
        }
    };
    auto issue_B = [&](int c) {
        const int kc = c * 64;
        const int s  = c & 1;
#pragma unroll
        for (int i = 0; i < 4; ++i) {
            int idx = tid + i * 256;
            int n = idx >> 3;                      // 0..127
            int u = idx & 7;
            uint32_t soff = (uint32_t)(n * 128 + ((u ^ (n & 7)) << 4));
            CP_ASYNC16(sbase + B_OFF(s) + soff, WT + (size_t)(col0 + n) * 256 + kc + u * 8);
        }
        CP_COMMIT();
    };

    // ---- prologue ----
    float4 rA[8];
    ldg_A(0, rA);
    issue_B(0);
    sts_A(0, rA);
    ldg_A(1, rA);

    for (int c = 0; c < 4; ++c) {
        CP_WAIT_0();
        __syncthreads();

        if (c < 3) issue_B(c + 1);

        const int s = c & 1;
        const uint32_t aBase = sbase + A_OFF(s);
        const uint32_t bBase = sbase + B_OFF(s);

#pragma unroll
        for (int kk = 0; kk < 4; ++kk) {
            uint32_t af[2][4];
#pragma unroll
            for (int mi = 0; mi < 2; ++mi) {
                int r = rA0 + mi * 16;
                uint32_t aoff = (uint32_t)(r * 128 + (((kk * 2 + uAbit) ^ lr) << 4));
                LDMATRIX_X4(af[mi][0], af[mi][1], af[mi][2], af[mi][3], aBase + aoff);
            }
#pragma unroll
            for (int np = 0; np < 4; ++np) {
                int n = nB0 + np * 16;
                uint32_t boff = (uint32_t)(n * 128 + (((kk * 2 + uBbit) ^ lr) << 4));
                uint32_t b0, b1r, b2, b3;
                LDMATRIX_X4(b0, b1r, b2, b3, bBase + boff);
#pragma unroll
                for (int mi = 0; mi < 2; ++mi) {
                    MMA_F16(acc[mi][np * 2],     af[mi][0], af[mi][1], af[mi][2], af[mi][3], b0, b1r);
                    MMA_F16(acc[mi][np * 2 + 1], af[mi][0], af[mi][1], af[mi][2], af[mi][3], b2, b3);
                }
            }
        }

        if (c < 3) {
            sts_A((c + 1) & 1, rA);
            if (c < 2) ldg_A(c + 2, rA);
        }
    }

    // ---- epilogue: +b1 on cols<128, store fp16 ----
    const int trow  = lane >> 2;
    const int tcol2 = (lane & 3) * 2;
#pragma unroll
    for (int mi = 0; mi < 2; ++mi) {
#pragma unroll
        for (int ni = 0; ni < 8; ++ni) {
            int col = col0 + wn * 64 + ni * 8 + tcol2;
            float bx = 0.f, by = 0.f;
            if (col < HH) { bx = __ldg(&b1[col]); by = __ldg(&b1[col + 1]); }
#pragma unroll
            for (int h = 0; h < 2; ++h) {
                int r = row0 + wm * 32 + mi * 16 + trow + h * 8;
                if (r < M) {
                    __half2 v = __floats2half2_rn(acc[mi][ni][h * 2] + bx,
                                                  acc[mi][ni][h * 2 + 1] + by);
                    *reinterpret_cast<__half2*>(UV + (size_t)r * 256 + col) = v;
                }
            }
        }
    }
}

// ---------------- Stage 2: 8 edges per warp, fp16 UV, L2-only gathers ----------------
__global__ __launch_bounds__(256)
void edge_kernel(const int* __restrict__ eli,
                 const __half* __restrict__ UV,
                 const float* __restrict__ W2,
                 const float* __restrict__ b2,
                 float* __restrict__ out,
                 int E) {
    int gwarp = (blockIdx.x * blockDim.x + threadIdx.x) >> 5;
    int lane  = threadIdx.x & 31;
    int e0 = gwarp * 8;
    if (e0 >= E) return;

    float4 w = __ldg(reinterpret_cast<const float4*>(W2) + lane);

    int s[8], d[8];
#pragma unroll
    for (int i = 0; i < 8; ++i) {
        int e = min(e0 + i, E - 1);
        s[i] = __ldg(&eli[e]);
        d[i] = __ldg(&eli[(size_t)E + e]);
    }
    uint2 ur[8], vr[8];
#pragma unroll
    for (int i = 0; i < 8; ++i) {
        ur[i] = __ldcg(reinterpret_cast<const uint2*>(UV + (size_t)s[i] * 256) + lane);
        vr[i] = __ldcg(reinterpret_cast<const uint2*>(UV + (size_t)d[i] * 256 + HH) + lane);
    }
    float p[8];
#pragma unroll
    for (int i = 0; i < 8; ++i) {
        const __half2* uh = reinterpret_cast<const __half2*>(&ur[i]);
        const __half2* vh = reinterpret_cast<const __half2*>(&vr[i]);
        float2 u01 = __half22float2(uh[0]);
        float2 u23 = __half22float2(uh[1]);
        float2 v01 = __half22float2(vh[0]);
        float2 v23 = __half22float2(vh[1]);
        p[i] = fmaxf(u01.x + v01.x, 0.f) * w.x + fmaxf(u01.y + v01.y, 0.f) * w.y
             + fmaxf(u23.x + v23.x, 0.f) * w.z + fmaxf(u23.y + v23.y, 0.f) * w.w;
    }
#pragma unroll
    for (int o = 16; o > 0; o >>= 1) {
#pragma unroll
        for (int i = 0; i < 8; ++i)
            p[i] += __shfl_down_sync(0xffffffffu, p[i], o);
    }
    if (lane == 0) {
        float bb = __ldg(b2);
#pragma unroll
        for (int i = 0; i < 8; ++i)
            if (e0 + i < E) out[e0 + i] = p[i] + bb;
    }
}

extern "C" void kernel_launch(void* const* d_in, const int* in_sizes, int n_in,
                              void* d_out, int out_size) {
    const float* z   = (const float*)d_in[0];
    const int*   eli = (const int*)d_in[1];
    const float* W1  = (const float*)d_in[2];
    const float* b1  = (const float*)d_in[3];
    const float* W2  = (const float*)d_in[4];
    const float* b2  = (const float*)d_in[5];
    float*       out = (float*)d_out;

    const int M = in_sizes[0] / DD;
    const int E = out_size;

    __half *UV, *WT;
    cudaGetSymbolAddress((void**)&UV, g_UV);
    cudaGetSymbolAddress((void**)&WT, g_WT);

    cudaFuncSetAttribute(uv_gemm_fused_kernel,
                         cudaFuncAttributeMaxDynamicSharedMemorySize, GSM_TOTAL);

    split_w_kernel<<<(256 * 256 + 255) / 256, 256>>>(W1, WT);

    dim3 ggrid((M + 127) / 128, 2);
    uv_gemm_fused_kernel<<<ggrid, 256, GSM_TOTAL>>>(z, WT, b1, UV, M);

    int octs = (E + 7) / 8;
    int warpsPerBlock = 256 / 32;
    int nblk = (octs + warpsPerBlock - 1) / warpsPerBlock;
    edge_kernel<<<nblk, 256>>>(eli, UV, W2, b2, out, E);
}

// round 15
// speedup vs baseline: 1.1682x; 1.0182x over previous
#include <cuda_runtime.h>
#include <cuda_bf16.h>
#include <cuda_fp16.h>
#include <cstdint>

// LinkPredictorGAT: N_NODES=100000, D=256, E=1000000, H=128
// out_e = relu(z[src]@W1[:256] + z[dst]@W1[256:] + b1) @ W2 + b2
//
// Stage 0: W1 -> WT fp16 (triggers PDL completion at start).
// Stage 1: fp16 HMMA GEMM (round-10/14 config), PDL: Z prologue loads overlap
//          split_w; gridDepSync before first WT read; triggers after mainloop.
// Stage 2: 8 edges/warp, __ldcg UV gathers, PDL: index/W2 preamble overlaps
//          GEMM epilogue; gridDepSync before first UV read.

#define MAX_NODES 100000
#define DD 256
#define HH 128

__device__ __half g_UV[(size_t)MAX_NODES * 2 * HH];     // 51.2 MB
__device__ __half g_WT[256 * 256];                      // 128 KB

__device__ __forceinline__ uint32_t smem_u32(const void* p) {
    uint32_t a;
    asm("{ .reg .u64 t; cvta.to.shared.u64 t, %1; cvt.u32.u64 %0, t; }" : "=r"(a) : "l"(p));
    return a;
}

#define CP_ASYNC16(dst, src) \
    asm volatile("cp.async.cg.shared.global [%0], [%1], 16;" :: "r"(dst), "l"(src) : "memory")
#define CP_COMMIT() asm volatile("cp.async.commit_group;" ::: "memory")
#define CP_WAIT_0() asm volatile("cp.async.wait_group 0;" ::: "memory")

#define LDMATRIX_X4(r0, r1, r2, r3, addr) \
    asm volatile("ldmatrix.sync.aligned.m8n8.x4.shared.b16 {%0,%1,%2,%3}, [%4];" \
                 : "=r"(r0), "=r"(r1), "=r"(r2), "=r"(r3) : "r"(addr))

#define MMA_F16(d, a0, a1, a2, a3, b0, b1) \
    asm volatile("mma.sync.aligned.m16n8k16.row.col.f32.f16.f16.f32 " \
                 "{%0,%1,%2,%3}, {%4,%5,%6,%7}, {%8,%9}, {%0,%1,%2,%3};" \
                 : "+f"((d)[0]), "+f"((d)[1]), "+f"((d)[2]), "+f"((d)[3]) \
                 : "r"(a0), "r"(a1), "r"(a2), "r"(a3), "r"(b0), "r"(b1))

// ---------------- Stage 0: build transposed fp16 W ----------------
__global__ __launch_bounds__(256)
void split_w_kernel(const float* __restrict__ W1, __half* __restrict__ WT) {
#if __CUDA_ARCH__ >= 900
    cudaTriggerProgrammaticLaunchCompletion();   // let GEMM launch immediately
#endif
    int idx = blockIdx.x * blockDim.x + threadIdx.x;
    if (idx >= 256 * 256) return;
    int n = idx & 255;
    int k = idx >> 8;
    float val = (n < HH) ? W1[(size_t)k * HH + n]
                         : W1[(size_t)(256 + k) * HH + (n - HH)];
    WT[(size_t)n * 256 + k] = __float2half_rn(val);
}

// ---------------- Stage 1: fp16 HMMA GEMM, 128x128 tile ----------------
// SMEM (64 KB), stages s in {0,1}:
//   A(s) @ s*16384                 [0, 32K)
//   B(s) @ 32768 + s*16384         [32K, 64K)
#define A_OFF(s)  ((s) * 16384)
#define B_OFF(s)  (32768 + (s) * 16384)
#define GSM_TOTAL 65536

__global__ __launch_bounds__(256, 2)
void uv_gemm_fused_kernel(const float* __restrict__ Z,
                          const __half* __restrict__ WT,
                          const float* __restrict__ b1,
                          __half* __restrict__ UV,
                          int M) {
    extern __shared__ char smem[];
    const uint32_t sbase = smem_u32(smem);
    const int tid  = threadIdx.x;
    const int wid  = tid >> 5;
    const int lane = tid & 31;
    const int wm   = wid & 3;          // 4 warp-row groups: 32 rows each
    const int wn   = wid >> 2;         // 2 warp-col groups: 64 cols each
    const int row0 = blockIdx.x * 128;
    const int col0 = blockIdx.y * 128; // N-half of WT

    const int g  = lane >> 3;
    const int lr = lane & 7;
    const int uAbit = g >> 1;
    const int uBbit = g & 1;
    const int rA0 = wm * 32 + (g & 1) * 8 + lr;
    const int nB0 = wn * 64 + (g >> 1) * 8 + lr;   // within 128-row B tile

    float acc[2][8][4];
#pragma unroll
    for (int mi = 0; mi < 2; mi++)
#pragma unroll
        for (int ni = 0; ni < 8; ni++)
#pragma unroll
            for (int q = 0; q < 4; q++) acc[mi][ni][q] = 0.f;

    auto ldg_A = [&](int c, float4 (&rA)[8]) {
        const int kc = c * 64;
#pragma unroll
        for (int i = 0; i < 8; ++i) {
            int idx = tid + i * 256;
            int r = idx >> 4;
            int q = idx & 15;
            int gr = row0 + r; if (gr > M - 1) gr = M - 1;
            rA[i] = __ldg(reinterpret_cast<const float4*>(Z + (size_t)gr * 256 + kc + q * 4));
        }
    };
    auto sts_A = [&](int s, const float4 (&rA)[8]) {
#pragma unroll
        for (int i = 0; i < 8; ++i) {
            int idx = tid + i * 256;
            int r = idx >> 4;
            int q = idx & 15;
            float4 f = rA[i];
            __half2 h01 = __floats2half2_rn(f.x, f.y);
            __half2 h23 = __floats2half2_rn(f.z, f.w);
            uint2 hv = make_uint2(*reinterpret_cast<uint32_t*>(&h01),
                                  *reinterpret_cast<uint32_t*>(&h23));
            uint32_t soff = (uint32_t)(r * 128 + (((q >> 1) ^ (r & 7)) << 4) + (q & 1) * 8);
            *reinterpret_cast<uint2*>(smem + A_OFF(s) + soff) = hv;
        }
    };
    auto issue_B = [&](int c) {
        const int kc = c * 64;
        const int s  = c & 1;
#pragma unroll
        for (int i = 0; i < 4; ++i) {
            int idx = tid + i * 256;
            int n = idx >> 3;                      // 0..127
            int u = idx & 7;
            uint32_t soff = (uint32_t)(n * 128 + ((u ^ (n & 7)) << 4));
            CP_ASYNC16(sbase + B_OFF(s) + soff, WT + (size_t)(col0 + n) * 256 + kc + u * 8);
        }
        CP_COMMIT();
    };

    // ---- prologue: Z loads are independent of split_w's WT ----
    float4 rA[8];
    ldg_A(0, rA);
#if __CUDA_ARCH__ >= 900
    cudaGridDependencySynchronize();   // WT ready beyond this point
#endif
    issue_B(0);
    sts_A(0, rA);
    ldg_A(1, rA);

    for (int c = 0; c < 4; ++c) {
        CP_WAIT_0();
        __syncthreads();

        if (c < 3) issue_B(c + 1);

        const int s = c & 1;
        const uint32_t aBase = sbase + A_OFF(s);
        const uint32_t bBase = sbase + B_OFF(s);

#pragma unroll
        for (int kk = 0; kk < 4; ++kk) {
            uint32_t af[2][4];
#pragma unroll
            for (int mi = 0; mi < 2; ++mi) {
                int r = rA0 + mi * 16;
                uint32_t aoff = (uint32_t)(r * 128 + (((kk * 2 + uAbit) ^ lr) << 4));
                LDMATRIX_X4(af[mi][0], af[mi][1], af[mi][2], af[mi][3], aBase + aoff);
            }
#pragma unroll
            for (int np = 0; np < 4; ++np) {
                int n = nB0 + np * 16;
                uint32_t boff = (uint32_t)(n * 128 + (((kk * 2 + uBbit) ^ lr) << 4));
                uint32_t b0, b1r, b2, b3;
                LDMATRIX_X4(b0, b1r, b2, b3, bBase + boff);
#pragma unroll
                for (int mi = 0; mi < 2; ++mi) {
                    MMA_F16(acc[mi][np * 2],     af[mi][0], af[mi][1], af[mi][2], af[mi][3], b0, b1r);
                    MMA_F16(acc[mi][np * 2 + 1], af[mi][0], af[mi][1], af[mi][2], af[mi][3], b2, b3);
                }
            }
        }

        if (c < 3) {
            sts_A((c + 1) & 1, rA);
            if (c < 2) ldg_A(c + 2, rA);
        }
    }

#if __CUDA_ARCH__ >= 900
    cudaTriggerProgrammaticLaunchCompletion();   // edge may launch; epilogue remains
#endif

    // ---- epilogue: +b1 on cols<128, store fp16 ----
    const int trow  = lane >> 2;
    const int tcol2 = (lane & 3) * 2;
#pragma unroll
    for (int mi = 0; mi < 2; ++mi) {
#pragma unroll
        for (int ni = 0; ni < 8; ++ni) {
            int col = col0 + wn * 64 + ni * 8 + tcol2;
            float bx = 0.f, by = 0.f;
            if (col < HH) { bx = __ldg(&b1[col]); by = __ldg(&b1[col + 1]); }
#pragma unroll
            for (int h = 0; h < 2; ++h) {
                int r = row0 + wm * 32 + mi * 16 + trow + h * 8;
                if (r < M) {
                    __half2 v = __floats2half2_rn(acc[mi][ni][h * 2] + bx,
                                                  acc[mi][ni][h * 2 + 1] + by);
                    *reinterpret_cast<__half2*>(UV + (size_t)r * 256 + col) = v;
                }
            }
        }
    }
}

// ---------------- Stage 2: 8 edges per warp, fp16 UV, L2-only gathers ----------------
__global__ __launch_bounds__(256)
void edge_kernel(const int* __restrict__ eli,
                 const __half* __restrict__ UV,
                 const float* __restrict__ W2,
                 const float* __restrict__ b2,
                 float* __restrict__ out,
                 int E) {
    int gwarp = (blockIdx.x * blockDim.x + threadIdx.x) >> 5;
    int lane  = threadIdx.x & 31;
    int e0 = gwarp * 8;
    if (e0 >= E) return;

    // preamble: independent of GEMM's UV
    float4 w = __ldg(reinterpret_cast<const float4*>(W2) + lane);
    float bb = __ldg(b2);

    int s[8], d[8];
#pragma unroll
    for (int i = 0; i < 8; ++i) {
        int e = min(e0 + i, E - 1);
        s[i] = __ldg(&eli[e]);
        d[i] = __ldg(&eli[(size_t)E + e]);
    }

#if __CUDA_ARCH__ >= 900
    cudaGridDependencySynchronize();   // UV ready beyond this point
#endif

    uint2 ur[8], vr[8];
#pragma unroll
    for (int i = 0; i < 8; ++i) {
        ur[i] = __ldcg(reinterpret_cast<const uint2*>(UV + (size_t)s[i] * 256) + lane);
        vr[i] = __ldcg(reinterpret_cast<const uint2*>(UV + (size_t)d[i] * 256 + HH) + lane);
    }
    float p[8];
#pragma unroll
    for (int i = 0; i < 8; ++i) {
        const __half2* uh = reinterpret_cast<const __half2*>(&ur[i]);
        const __half2* vh = reinterpret_cast<const __half2*>(&vr[i]);
        float2 u01 = __half22float2(uh[0]);
        float2 u23 = __half22float2(uh[1]);
        float2 v01 = __half22float2(vh[0]);
        float2 v23 = __half22float2(vh[1]);
        p[i] = fmaxf(u01.x + v01.x, 0.f) * w.x + fmaxf(u01.y + v01.y, 0.f) * w.y
             + fmaxf(u23.x + v23.x, 0.f) * w.z + fmaxf(u23.y + v23.y, 0.f) * w.w;
    }
#pragma unroll
    for (int o = 16; o > 0; o >>= 1) {
#pragma unroll
        for (int i = 0; i < 8; ++i)
            p[i] += __shfl_down_sync(0xffffffffu, p[i], o);
    }
    if (lane == 0) {
#pragma unroll
        for (int i = 0; i < 8; ++i)
            if (e0 + i < E) out[e0 + i] = p[i] + bb;
    }
}

extern "C" void kernel_launch(void* const* d_in, const int* in_sizes, int n_in,
                              void* d_out, int out_size) {
    const float* z   = (const float*)d_in[0];
    const int*   eli = (const int*)d_in[1];
    const float* W1  = (const float*)d_in[2];
    const float* b1  = (const float*)d_in[3];
    const float* W2  = (const float*)d_in[4];
    const float* b2  = (const float*)d_in[5];
    float*       out = (float*)d_out;

    const int M = in_sizes[0] / DD;
    const int E = out_size;

    __half *UV, *WT;
    cudaGetSymbolAddress((void**)&UV, g_UV);
    cudaGetSymbolAddress((void**)&WT, g_WT);

    cudaFuncSetAttribute(uv_gemm_fused_kernel,
                         cudaFuncAttributeMaxDynamicSharedMemorySize, GSM_TOTAL);

    // kernel 1: split_w (plain launch)
    split_w_kernel<<<(256 * 256 + 255) / 256, 256>>>(W1, WT);

    // kernel 2: GEMM with PDL serialization against split_w
    {
        cudaLaunchConfig_t cfg = {};
        cfg.gridDim  = dim3((M + 127) / 128, 2, 1);
        cfg.blockDim = dim3(256, 1, 1);
        cfg.dynamicSmemBytes = GSM_TOTAL;
        cudaLaunchAttribute attrs[1];
        attrs[0].id = cudaLaunchAttributeProgrammaticStreamSerialization;
        attrs[0].val.programmaticStreamSerializationAllowed = 1;
        cfg.attrs = attrs;
        cfg.numAttrs = 1;
        cudaLaunchKernelEx(&cfg, uv_gemm_fused_kernel, z, WT, b1, UV, M);
    }

    // kernel 3: edge with PDL serialization against GEMM
    {
        int octs = (E + 7) / 8;
        int warpsPerBlock = 256 / 32;
        int nblk = (octs + warpsPerBlock - 1) / warpsPerBlock;
        cudaLaunchConfig_t cfg = {};
        cfg.gridDim  = dim3(nblk, 1, 1);
        cfg.blockDim = dim3(256, 1, 1);
        cfg.dynamicSmemBytes = 0;
        cudaLaunchAttribute attrs[1];
        attrs[0].id = cudaLaunchAttributeProgrammaticStreamSerialization;
        attrs[0].val.programmaticStreamSerializationAllowed = 1;
        cfg.attrs = attrs;
        cfg.numAttrs = 1;
        cudaLaunchKernelEx(&cfg, edge_kernel, eli, UV, W2, b2, out, E);
    }
}

// round 16
// speedup vs baseline: 1.1685x; 1.0003x over previous
#include <cuda_runtime.h>
#include <cuda_bf16.h>
#include <cuda_fp16.h>
#include <cstdint>

// LinkPredictorGAT: N_NODES=100000, D=256, E=1000000, H=128
// out_e = relu(z[src]@W1[:256] + z[dst]@W1[256:] + b1) @ W2 + b2
//
// Stage 0: W1 -> WT fp16; PDL trigger AFTER the WT store (race-free handoff).
// Stage 1: fp16 HMMA GEMM (round-10/14 config). Full A-prologue (ldg/sts/ldg)
//          runs before gridDepSync (WT-independent), maximizing split_w overlap.
//          PDL trigger AFTER the UV epilogue stores (race-free handoff).
// Stage 2: 8 edges/warp, __ldcg UV gathers; index/W2 preamble before gridDepSync.

#define MAX_NODES 100000
#define DD 256
#define HH 128

__device__ __half g_UV[(size_t)MAX_NODES * 2 * HH];     // 51.2 MB
__device__ __half g_WT[256 * 256];                      // 128 KB

__device__ __forceinline__ uint32_t smem_u32(const void* p) {
    uint32_t a;
    asm("{ .reg .u64 t; cvta.to.shared.u64 t, %1; cvt.u32.u64 %0, t; }" : "=r"(a) : "l"(p));
    return a;
}

#define CP_ASYNC16(dst, src) \
    asm volatile("cp.async.cg.shared.global [%0], [%1], 16;" :: "r"(dst), "l"(src) : "memory")
#define CP_COMMIT() asm volatile("cp.async.commit_group;" ::: "memory")
#define CP_WAIT_0() asm volatile("cp.async.wait_group 0;" ::: "memory")

#define LDMATRIX_X4(r0, r1, r2, r3, addr) \
    asm volatile("ldmatrix.sync.aligned.m8n8.x4.shared.b16 {%0,%1,%2,%3}, [%4];" \
                 : "=r"(r0), "=r"(r1), "=r"(r2), "=r"(r3) : "r"(addr))

#define MMA_F16(d, a0, a1, a2, a3, b0, b1) \
    asm volatile("mma.sync.aligned.m16n8k16.row.col.f32.f16.f16.f32 " \
                 "{%0,%1,%2,%3}, {%4,%5,%6,%7}, {%8,%9}, {%0,%1,%2,%3};" \
                 : "+f"((d)[0]), "+f"((d)[1]), "+f"((d)[2]), "+f"((d)[3]) \
                 : "r"(a0), "r"(a1), "r"(a2), "r"(a3), "r"(b0), "r"(b1))

// ---------------- Stage 0: build transposed fp16 W ----------------
__global__ __launch_bounds__(256)
void split_w_kernel(const float* __restrict__ W1, __half* __restrict__ WT) {
    int idx = blockIdx.x * blockDim.x + threadIdx.x;
    if (idx < 256 * 256) {
        int n = idx & 255;
        int k = idx >> 8;
        float val = (n < HH) ? W1[(size_t)k * HH + n]
                             : W1[(size_t)(256 + k) * HH + (n - HH)];
        WT[(size_t)n * 256 + k] = __float2half_rn(val);
    }
#if __CUDA_ARCH__ >= 900
    cudaTriggerProgrammaticLaunchCompletion();   // AFTER the store: WT valid
#endif
}

// ---------------- Stage 1: fp16 HMMA GEMM, 128x128 tile ----------------
// SMEM (64 KB), stages s in {0,1}:
//   A(s) @ s*16384                 [0, 32K)
//   B(s) @ 32768 + s*16384         [32K, 64K)
#define A_OFF(s)  ((s) * 16384)
#define B_OFF(s)  (32768 + (s) * 16384)
#define GSM_TOTAL 65536

__global__ __launch_bounds__(256, 2)
void uv_gemm_fused_kernel(const float* __restrict__ Z,
                          const __half* __restrict__ WT,
                          const float* __restrict__ b1,
                          __half* __restrict__ UV,
                          int M) {
    extern __shared__ char smem[];
    const uint32_t sbase = smem_u32(smem);
    const int tid  = threadIdx.x;
    const int wid  = tid >> 5;
    const int lane = tid & 31;
    const int wm   = wid & 3;          // 4 warp-row groups: 32 rows each
    const int wn   = wid >> 2;         // 2 warp-col groups: 64 cols each
    const int row0 = blockIdx.x * 128;
    const int col0 = blockIdx.y * 128; // N-half of WT

    const int g  = lane >> 3;
    const int lr = lane & 7;
    const int uAbit = g >> 1;
    const int uBbit = g & 1;
    const int rA0 = wm * 32 + (g & 1) * 8 + lr;
    const int nB0 = wn * 64 + (g >> 1) * 8 + lr;   // within 128-row B tile

    float acc[2][8][4];
#pragma unroll
    for (int mi = 0; mi < 2; mi++)
#pragma unroll
        for (int ni = 0; ni < 8; ni++)
#pragma unroll
            for (int q = 0; q < 4; q++) acc[mi][ni][q] = 0.f;

    auto ldg_A = [&](int c, float4 (&rA)[8]) {
        const int kc = c * 64;
#pragma unroll
        for (int i = 0; i < 8; ++i) {
            int idx = tid + i * 256;
            int r = idx >> 4;
            int q = idx & 15;
            int gr = row0 + r; if (gr > M - 1) gr = M - 1;
            rA[i] = __ldg(reinterpret_cast<const float4*>(Z + (size_t)gr * 256 + kc + q * 4));
        }
    };
    auto sts_A = [&](int s, const float4 (&rA)[8]) {
#pragma unroll
        for (int i = 0; i < 8; ++i) {
            int idx = tid + i * 256;
            int r = idx >> 4;
            int q = idx & 15;
            float4 f = rA[i];
            __half2 h01 = __floats2half2_rn(f.x, f.y);
            __half2 h23 = __floats2half2_rn(f.z, f.w);
            uint2 hv = make_uint2(*reinterpret_cast<uint32_t*>(&h01),
                                  *reinterpret_cast<uint32_t*>(&h23));
            uint32_t soff = (uint32_t)(r * 128 + (((q >> 1) ^ (r & 7)) << 4) + (q & 1) * 8);
            *reinterpret_cast<uint2*>(smem + A_OFF(s) + soff) = hv;
        }
    };
    auto issue_B = [&](int c) {
        const int kc = c * 64;
        const int s  = c & 1;
#pragma unroll
        for (int i = 0; i < 4; ++i) {
            int idx = tid + i * 256;
            int n = idx >> 3;                      // 0..127
            int u = idx & 7;
            uint32_t soff = (uint32_t)(n * 128 + ((u ^ (n & 7)) << 4));
            CP_ASYNC16(sbase + B_OFF(s) + soff, WT + (size_t)(col0 + n) * 256 + kc + u * 8);
        }
        CP_COMMIT();
    };

    // ---- prologue: entire A path is WT-independent -> run before gridDepSync ----
    float4 rA[8];
    ldg_A(0, rA);
    sts_A(0, rA);
    ldg_A(1, rA);
#if __CUDA_ARCH__ >= 900
    cudaGridDependencySynchronize();   // WT guaranteed written beyond this point
#endif
    issue_B(0);

    for (int c = 0; c < 4; ++c) {
        CP_WAIT_0();
        __syncthreads();

        if (c < 3) issue_B(c + 1);

        const int s = c & 1;
        const uint32_t aBase = sbase + A_OFF(s);
        const uint32_t bBase = sbase + B_OFF(s);

#pragma unroll
        for (int kk = 0; kk < 4; ++kk) {
            uint32_t af[2][4];
#pragma unroll
            for (int mi = 0; mi < 2; ++mi) {
                int r = rA0 + mi * 16;
                uint32_t aoff = (uint32_t)(r * 128 + (((kk * 2 + uAbit) ^ lr) << 4));
                LDMATRIX_X4(af[mi][0], af[mi][1], af[mi][2], af[mi][3], aBase + aoff);
            }
#pragma unroll
            for (int np = 0; np < 4; ++np) {
                int n = nB0 + np * 16;
                uint32_t boff = (uint32_t)(n * 128 + (((kk * 2 + uBbit) ^ lr) << 4));
                uint32_t b0, b1r, b2, b3;
                LDMATRIX_X4(b0, b1r, b2, b3, bBase + boff);
#pragma unroll
                for (int mi = 0; mi < 2; ++mi) {
                    MMA_F16(acc[mi][np * 2],     af[mi][0], af[mi][1], af[mi][2], af[mi][3], b0, b1r);
                    MMA_F16(acc[mi][np * 2 + 1], af[mi][0], af[mi][1], af[mi][2], af[mi][3], b2, b3);
                }
            }
        }

        if (c < 3) {
            sts_A((c + 1) & 1, rA);
            if (c < 2) ldg_A(c + 2, rA);
        }
    }

    // ---- epilogue: +b1 on cols<128, store fp16 ----
    const int trow  = lane >> 2;
    const int tcol2 = (lane & 3) * 2;
#pragma unroll
    for (int mi = 0; mi < 2; ++mi) {
#pragma unroll
        for (int ni = 0; ni < 8; ++ni) {
            int col = col0 + wn * 64 + ni * 8 + tcol2;
            float bx = 0.f, by = 0.f;
            if (col < HH) { bx = __ldg(&b1[col]); by = __ldg(&b1[col + 1]); }
#pragma unroll
            for (int h = 0; h < 2; ++h) {
                int r = row0 + wm * 32 + mi * 16 + trow + h * 8;
                if (r < M) {
                    __half2 v = __floats2half2_rn(acc[mi][ni][h * 2] + bx,
                                                  acc[mi][ni][h * 2 + 1] + by);
                    *reinterpret_cast<__half2*>(UV + (size_t)r * 256 + col) = v;
                }
            }
        }
    }

#if __CUDA_ARCH__ >= 900
    cudaTriggerProgrammaticLaunchCompletion();   // AFTER UV stores: race-free
#endif
}

// ---------------- Stage 2: 8 edges per warp, fp16 UV, L2-only gathers ----------------
__global__ __launch_bounds__(256)
void edge_kernel(const int* __restrict__ eli,
                 const __half* __restrict__ UV,
                 const float* __restrict__ W2,
                 const float* __restrict__ b2,
                 float* __restrict__ out,
                 int E) {
    int gwarp = (blockIdx.x * blockDim.x + threadIdx.x) >> 5;
    int lane  = threadIdx.x & 31;
    int e0 = gwarp * 8;
    if (e0 >= E) return;

    // preamble: independent of GEMM's UV
    float4 w = __ldg(reinterpret_cast<const float4*>(W2) + lane);
    float bb = __ldg(b2);

    int s[8], d[8];
#pragma unroll
    for (int i = 0; i < 8; ++i) {
        int e = min(e0 + i, E - 1);
        s[i] = __ldg(&eli[e]);
        d[i] = __ldg(&eli[(size_t)E + e]);
    }

#if __CUDA_ARCH__ >= 900
    cudaGridDependencySynchronize();   // UV guaranteed written beyond this point
#endif

    uint2 ur[8], vr[8];
#pragma unroll
    for (int i = 0; i < 8; ++i) {
        ur[i] = __ldcg(reinterpret_cast<const uint2*>(UV + (size_t)s[i] * 256) + lane);
        vr[i] = __ldcg(reinterpret_cast<const uint2*>(UV + (size_t)d[i] * 256 + HH) + lane);
    }
    float p[8];
#pragma unroll
    for (int i = 0; i < 8; ++i) {
        const __half2* uh = reinterpret_cast<const __half2*>(&ur[i]);
        const __half2* vh = reinterpret_cast<const __half2*>(&vr[i]);
        float2 u01 = __half22float2(uh[0]);
        float2 u23 = __half22float2(uh[1]);
        float2 v01 = __half22float2(vh[0]);
        float2 v23 = __half22float2(vh[1]);
        p[i] = fmaxf(u01.x + v01.x, 0.f) * w.x + fmaxf(u01.y + v01.y, 0.f) * w.y
             + fmaxf(u23.x + v23.x, 0.f) * w.z + fmaxf(u23.y + v23.y, 0.f) * w.w;
    }
#pragma unroll
    for (int o = 16; o > 0; o >>= 1) {
#pragma unroll
        for (int i = 0; i < 8; ++i)
            p[i] += __shfl_down_sync(0xffffffffu, p[i], o);
    }
    if (lane == 0) {
#pragma unroll
        for (int i = 0; i < 8; ++i)
            if (e0 + i < E) out[e0 + i] = p[i] + bb;
    }
}

extern "C" void kernel_launch(void* const* d_in, const int* in_sizes, int n_in,
                              void* d_out, int out_size) {
    const float* z   = (const float*)d_in[0];
    const int*   eli = (const int*)d_in[1];
    const float* W1  = (const float*)d_in[2];
    const float* b1  = (const float*)d_in[3];
    const float* W2  = (const float*)d_in[4];
    const float* b2  = (const float*)d_in[5];
    float*       out = (float*)d_out;

    const int M = in_sizes[0] / DD;
    const int E = out_size;

    __half *UV, *WT;
    cudaGetSymbolAddress((void**)&UV, g_UV);
    cudaGetSymbolAddress((void**)&WT, g_WT);

    cudaFuncSetAttribute(uv_gemm_fused_kernel,
                         cudaFuncAttributeMaxDynamicSharedMemorySize, GSM_TOTAL);

    // kernel 1: split_w (plain launch)
    split_w_kernel<<<(256 * 256 + 255) / 256, 256>>>(W1, WT);

    // kernel 2: GEMM with PDL serialization against split_w
    {
        cudaLaunchConfig_t cfg = {};
        cfg.gridDim  = dim3((M + 127) / 128, 2, 1);
        cfg.blockDim = dim3(256, 1, 1);
        cfg.dynamicSmemBytes = GSM_TOTAL;
        cudaLaunchAttribute attrs[1];
        attrs[0].id = cudaLaunchAttributeProgrammaticStreamSerialization;
        attrs[0].val.programmaticStreamSerializationAllowed = 1;
        cfg.attrs = attrs;
        cfg.numAttrs = 1;
        cudaLaunchKernelEx(&cfg, uv_gemm_fused_kernel, z, WT, b1, UV, M);
    }

    // kernel 3: edge with PDL serialization against GEMM
    {
        int octs = (E + 7) / 8;
        int warpsPerBlock = 256 / 32;
        int nblk = (octs + warpsPerBlock - 1) / warpsPerBlock;
        cudaLaunchConfig_t cfg = {};
        cfg.gridDim  = dim3(nblk, 1, 1);
        cfg.blockDim = dim3(256, 1, 1);
        cfg.dynamicSmemBytes = 0;
        cudaLaunchAttribute attrs[1];
        attrs[0].id = cudaLaunchAttributeProgrammaticStreamSerialization;
        attrs[0].val.programmaticStreamSerializationAllowed = 1;
        cfg.attrs = attrs;
        cfg.numAttrs = 1;
        cudaLaunchKernelEx(&cfg, edge_kernel, eli, UV, W2, b2, out, E);
    }
}